// round 8
// baseline (speedup 1.0000x reference)
#include <cuda_runtime.h>
#include <cuda_fp16.h>
#include <cstdint>

#define NUM_CODES 512
#define DIMS      64
#define HT        4096
#define N_VEC     131072
#define ZQ_SIZE   8388608
#define CTA_M     256
#define THREADS   512
#define GRID      148
#define NTILES    512

// ---- dynamic smem layout (bytes), MMA regions 1024-aligned for SW128 ----
#define SM_AHI   0
#define SM_ALO   32768
#define SM_BHI   65536
#define SM_BLO   131072
#define SM_BI    196608
#define SM_WSUM  197632
#define SM_RED   197696          // 512 floats for in-kernel finalize
#define SMEM_TOTAL 199744

__device__ float g_part[GRID];        // zero-init; overwritten every call
__device__ int   g_counts[NUM_CODES]; // zero-init; reset by finalize branch
__device__ int   g_done;              // zero-init; reset by finalize branch

#define SW(x) ((x) ^ ((((uint32_t)(x)) >> 3) & 0x70))

__device__ __forceinline__ uint32_t smem_u32(const void* p) {
    uint32_t a;
    asm("{ .reg .u64 t; cvta.to.shared.u64 t, %1; cvt.u32.u64 %0, t; }" : "=r"(a) : "l"(p));
    return a;
}
__device__ __forceinline__ void ldsm_x4(uint32_t& r0, uint32_t& r1, uint32_t& r2, uint32_t& r3, uint32_t a) {
    asm volatile("ldmatrix.sync.aligned.m8n8.x4.shared.b16 {%0,%1,%2,%3}, [%4];"
                 : "=r"(r0), "=r"(r1), "=r"(r2), "=r"(r3) : "r"(a));
}
__device__ __forceinline__ void mma16816(float* c, const uint32_t* a, uint32_t b0, uint32_t b1) {
    asm volatile("mma.sync.aligned.m16n8k16.row.col.f32.f16.f16.f32 "
                 "{%0,%1,%2,%3}, {%4,%5,%6,%7}, {%8,%9}, {%0,%1,%2,%3};"
                 : "+f"(c[0]), "+f"(c[1]), "+f"(c[2]), "+f"(c[3])
                 : "r"(a[0]), "r"(a[1]), "r"(a[2]), "r"(a[3]), "r"(b0), "r"(b1));
}
__device__ __forceinline__ uint32_t h2u(__half2 h) { return reinterpret_cast<uint32_t&>(h); }
__device__ __forceinline__ float2   u2f(uint32_t u) { __half2 h = reinterpret_cast<__half2&>(u); return __half22float2(h); }

__global__ __launch_bounds__(THREADS, 1) void vq_main(
    const float* __restrict__ z_e, const float* __restrict__ embed,
    float* __restrict__ out)
{
    extern __shared__ char smem[];
    const uint32_t sbase = smem_u32(smem);
    const int tid = threadIdx.x, wid = tid >> 5, lid = tid & 31;

    // ---------- B fill ONCE: embedding (512x64 fp32) -> f16 hi/lo, SW128 ----------
    {
        const float4* e4 = (const float4*)embed;
        #pragma unroll 4
        for (int i = tid; i < NUM_CODES * DIMS / 4; i += THREADS) {
            float4 f = e4[i];
            int row = i >> 4, dg = i & 15;
            __half hx = __float2half_rn(f.x), hy = __float2half_rn(f.y);
            __half hz = __float2half_rn(f.z), hw = __float2half_rn(f.w);
            __half lx = __float2half_rn(f.x - __half2float(hx));
            __half ly = __float2half_rn(f.y - __half2float(hy));
            __half lz = __float2half_rn(f.z - __half2float(hz));
            __half lw = __float2half_rn(f.w - __half2float(hw));
            uint32_t off = SW(row * 128 + dg * 8);
            *(uint2*)(smem + SM_BHI + off) = make_uint2(h2u(__halves2half2(hx, hy)), h2u(__halves2half2(hz, hw)));
            *(uint2*)(smem + SM_BLO + off) = make_uint2(h2u(__halves2half2(lx, ly)), h2u(__halves2half2(lz, lw)));
        }
    }

    const int rbase = wid * 16;              // 16 rows per warp (one m-tile)
    const int arow = tid >> 1;               // A-fill / epilogue: half row per thread
    const int ahalf = tid & 1;               // dims [ahalf*32, ahalf*32+32)
    int* sBI = (int*)(smem + SM_BI);
    float csum_total = 0.f;

    // ================= persistent tile loop =================
    for (int tile = blockIdx.x; tile < NTILES; tile += GRID) {
        // ---------- A fill: half-row per thread -> f16 hi/lo, SW128 ----------
        const int n = tile * CTA_M + arow;
        const int b = n >> 12, r = n & 4095;
        const float* zp = z_e + (size_t)b * (DIMS * HT) + r + (size_t)(ahalf * 32) * HT;

        #pragma unroll
        for (int i = 0; i < 4; i++) {
            uint32_t zh[4], zl[4];
            #pragma unroll
            for (int j = 0; j < 4; j++) {
                float x0 = zp[(8 * i + 2 * j) * HT];
                float x1 = zp[(8 * i + 2 * j + 1) * HT];
                __half h0 = __float2half_rn(x0), h1 = __float2half_rn(x1);
                __half l0 = __float2half_rn(x0 - __half2float(h0));
                __half l1 = __float2half_rn(x1 - __half2float(h1));
                zh[j] = h2u(__halves2half2(h0, h1));
                zl[j] = h2u(__halves2half2(l0, l1));
            }
            uint32_t off = SW(arow * 128 + ahalf * 64 + i * 16);
            *(uint4*)(smem + SM_AHI + off) = make_uint4(zh[0], zh[1], zh[2], zh[3]);
            *(uint4*)(smem + SM_ALO + off) = make_uint4(zl[0], zl[1], zl[2], zl[3]);
        }
        __syncthreads();   // A (and on iter 0, B) ready

        // ---------- A fragments: one m-tile per warp ----------
        uint32_t a_hi[4][4], a_lo[4][4];
        {
            uint32_t row = rbase + ((lid >> 3) & 1) * 8 + (lid & 7);
            uint32_t cg  = (lid >> 4) << 4;
            #pragma unroll
            for (int kt = 0; kt < 4; kt++) {
                uint32_t sw = SW(row * 128 + kt * 32 + cg);
                ldsm_x4(a_hi[kt][0], a_hi[kt][1], a_hi[kt][2], a_hi[kt][3], sbase + SM_AHI + sw);
                ldsm_x4(a_lo[kt][0], a_lo[kt][1], a_lo[kt][2], a_lo[kt][3], sbase + SM_ALO + sw);
            }
        }

        // ---------- main loop: 32 n-tile pairs, 3-pass, argmax(dot) ----------
        float m1[2] = {-3.4e38f, -3.4e38f};
        int   i1[2] = {0, 0};
        const uint32_t brow = ((lid >> 4) << 3) + (lid & 7);
        const uint32_t bk_off = ((lid >> 3) & 1) << 4;

        #pragma unroll 2
        for (int ntp = 0; ntp < 32; ntp++) {
            float acc[2][4] = {{0.f,0.f,0.f,0.f},{0.f,0.f,0.f,0.f}};
            #pragma unroll
            for (int kt = 0; kt < 4; kt++) {
                uint32_t byte = (ntp * 16 + brow) * 128 + kt * 32 + bk_off;
                uint32_t sw = SW(byte);
                uint32_t bh0, bh1, bh2, bh3, bl0, bl1, bl2, bl3;
                ldsm_x4(bh0, bh1, bh2, bh3, sbase + SM_BHI + sw);
                ldsm_x4(bl0, bl1, bl2, bl3, sbase + SM_BLO + sw);
                mma16816(acc[0], a_hi[kt], bh0, bh1);
                mma16816(acc[1], a_hi[kt], bh2, bh3);
                mma16816(acc[0], a_hi[kt], bl0, bl1);
                mma16816(acc[1], a_hi[kt], bl2, bl3);
                mma16816(acc[0], a_lo[kt], bh0, bh1);
                mma16816(acc[1], a_lo[kt], bh2, bh3);
            }
            #pragma unroll
            for (int h = 0; h < 2; h++)
                #pragma unroll
                for (int i = 0; i < 4; i++) {
                    int s = i >> 1;
                    int k = ntp * 16 + h * 8 + 2 * (lid & 3) + (i & 1);
                    float dot = acc[h][i];
                    if (dot > m1[s]) { m1[s] = dot; i1[s] = k; }
                }
        }

        // ---------- merge max(dot) across the 4 quad lanes ----------
        #pragma unroll
        for (int off = 1; off <= 2; off <<= 1) {
            #pragma unroll
            for (int s = 0; s < 2; s++) {
                float om = __shfl_xor_sync(0xffffffffu, m1[s], off);
                int   oi = __shfl_xor_sync(0xffffffffu, i1[s], off);
                bool take = (om > m1[s]) || (om == m1[s] && oi < i1[s]);
                if (take) { m1[s] = om; i1[s] = oi; }
            }
        }
        if ((lid & 3) == 0) {
            sBI[rbase + (lid >> 2)]     = i1[0];
            sBI[rbase + 8 + (lid >> 2)] = i1[1];
        }
        __syncthreads();

        // ---------- outputs (half-row per thread) ----------
        const int bi = sBI[arow];
        float* op = out + (size_t)b * (DIMS * HT) + r + (size_t)(ahalf * 32) * HT;
        float csum = 0.f;
        #pragma unroll
        for (int dg = 0; dg < 8; dg++) {
            uint32_t zo = SW(arow * 128 + ahalf * 64 + dg * 8);
            uint2 zh = *(uint2*)(smem + SM_AHI + zo);
            uint2 zl = *(uint2*)(smem + SM_ALO + zo);
            float2 z01 = u2f(zh.x), zl01 = u2f(zl.x), z23 = u2f(zh.y), zl23 = u2f(zl.y);
            float zv0 = z01.x + zl01.x, zv1 = z01.y + zl01.y;
            float zv2 = z23.x + zl23.x, zv3 = z23.y + zl23.y;
            uint32_t qo = SW(bi * 128 + ahalf * 64 + dg * 8);
            uint2 qh = *(uint2*)(smem + SM_BHI + qo);
            uint2 ql = *(uint2*)(smem + SM_BLO + qo);
            float2 e01 = u2f(qh.x), el01 = u2f(ql.x), e23 = u2f(qh.y), el23 = u2f(ql.y);
            float q0 = e01.x + el01.x, q1 = e01.y + el01.y, q2 = e23.x + el23.x, q3 = e23.y + el23.y;
            float d0 = q0 - zv0, d1v = q1 - zv1, d2v = q2 - zv2, d3 = q3 - zv3;
            op[(4 * dg + 0) * HT] = zv0 + d0;
            op[(4 * dg + 1) * HT] = zv1 + d1v;
            op[(4 * dg + 2) * HT] = zv2 + d2v;
            op[(4 * dg + 3) * HT] = zv3 + d3;
            csum += d0 * d0 + d1v * d1v + d2v * d2v + d3 * d3;
        }
        if (ahalf == 0) {
            out[ZQ_SIZE + 1 + n] = (float)bi;
            atomicAdd(&g_counts[bi], 1);
        }
        csum_total += csum;

        __syncthreads();   // protect A smem / sBI before next tile
    }

    // ---------- per-CTA commitment partial ----------
    #pragma unroll
    for (int off = 16; off; off >>= 1)
        csum_total += __shfl_down_sync(0xffffffffu, csum_total, off);
    float* wsum = (float*)(smem + SM_WSUM);
    if (lid == 0) wsum[wid] = csum_total;
    __syncthreads();
    if (tid == 0) {
        float s = 0.f;
        #pragma unroll
        for (int w = 0; w < 16; w++) s += wsum[w];
        g_part[blockIdx.x] = s;
    }

    // ---------- last-CTA in-kernel finalize ----------
    __threadfence();
    __shared__ int s_last;
    if (tid == 0) s_last = (atomicAdd(&g_done, 1) == GRID - 1);
    __syncthreads();
    if (s_last) {
        __threadfence();
        float* red = (float*)(smem + SM_RED);

        // commitment
        red[tid] = (tid < GRID) ? g_part[tid] : 0.f;
        __syncthreads();
        #pragma unroll
        for (int off = 256; off; off >>= 1) {
            if (tid < off) red[tid] += red[tid + off];
            __syncthreads();
        }
        if (tid == 0) out[ZQ_SIZE] = 0.25f * red[0] / (float)ZQ_SIZE;
        __syncthreads();

        // entropy -> perplexity
        const int c = g_counts[tid];
        {
            float p = (float)c / (float)N_VEC;
            red[tid] = -p * logf(p + 1e-12f);
        }
        __syncthreads();
        #pragma unroll
        for (int off = 256; off; off >>= 1) {
            if (tid < off) red[tid] += red[tid + off];
            __syncthreads();
        }
        if (tid == 0) out[ZQ_SIZE + 1 + N_VEC] = expf(red[0]);
        __syncthreads();

        // usage
        red[tid] = (c > 0) ? 1.f : 0.f;
        __syncthreads();
        #pragma unroll
        for (int off = 256; off; off >>= 1) {
            if (tid < off) red[tid] += red[tid + off];
            __syncthreads();
        }
        if (tid == 0) out[ZQ_SIZE + 1 + N_VEC + 1] = red[0] / (float)NUM_CODES;

        // reset state for next graph replay
        g_counts[tid] = 0;
        if (tid == 0) g_done = 0;
    }
}

extern "C" void kernel_launch(void* const* d_in, const int* in_sizes, int n_in,
                              void* d_out, int out_size) {
    const float* z_e   = (const float*)d_in[0];
    const float* embed = (const float*)d_in[1];
    float* out = (float*)d_out;

    cudaFuncSetAttribute(vq_main, cudaFuncAttributeMaxDynamicSharedMemorySize, SMEM_TOTAL);
    vq_main<<<GRID, THREADS, SMEM_TOTAL>>>(z_e, embed, out);
}